// round 1
// baseline (speedup 1.0000x reference)
#include <cuda_runtime.h>

// SlidingWindow: k,v (1, 2048, 16, 64) fp32, W=64
// out = concat(k_win, v_win), each (1, 2048, 16, 64, 64) fp32 layout [t][h][w][d]
// out_k[t,h,w,d] = (w < min(t+1,W)) ? k[max(0,t+1-W)+w, h, d] : 0

#define T_DIM 2048
#define H_DIM 16
#define D_DIM 64
#define W_DIM 64

// per-tensor float4 count: 2048*16*64*64/4 = 33,554,432
#define N4 33554432

__global__ __launch_bounds__(256) void sliding_window_kernel(
    const float4* __restrict__ k4,
    const float4* __restrict__ v4,
    float4* __restrict__ out4)   // [0, N4) = k_win, [N4, 2N4) = v_win
{
    const long long i = (long long)blockIdx.x * blockDim.x + threadIdx.x;
    if (i >= N4) return;

    // decompose: d4 fastest (16), then w (64), then h (16), then t
    const int d4 = (int)(i & 15);
    const int w  = (int)((i >> 4) & 63);
    const int h  = (int)((i >> 10) & 15);
    const int t  = (int)(i >> 14);

    // start = max(0, t+1-W); src = start + w; valid = w < min(t+1, W)
    const int start = (t >= W_DIM - 1) ? (t + 1 - W_DIM) : 0;
    const bool valid = (t >= W_DIM - 1) || (w <= t);
    const int src_t = start + w;

    // source float4 index: ((src_t*H + h)*D)/4 + d4 = ((src_t*16 + h) << 4) + d4
    const long long src = (((long long)src_t * H_DIM + h) << 4) + d4;

    float4 kk, vv;
    if (valid) {
        kk = __ldg(&k4[src]);
        vv = __ldg(&v4[src]);
    } else {
        kk = make_float4(0.f, 0.f, 0.f, 0.f);
        vv = kk;
    }

    out4[i]                    = kk;
    out4[i + (long long)N4]    = vv;
}

extern "C" void kernel_launch(void* const* d_in, const int* in_sizes, int n_in,
                              void* d_out, int out_size) {
    const float4* k4 = (const float4*)d_in[0];
    const float4* v4 = (const float4*)d_in[1];
    float4* out4 = (float4*)d_out;

    const int threads = 256;
    const int blocks = N4 / threads;  // 131072
    sliding_window_kernel<<<blocks, threads>>>(k4, v4, out4);
}